// round 2
// baseline (speedup 1.0000x reference)
#include <cuda_runtime.h>

#define NN   100000
#define EE   1600000
#define FIN  128
#define FOUT 32

// ---------------- scratch (device globals; no allocation) ----------------
__device__ float g_inv_sigma;
__device__ float g_xw[NN * FOUT];   // 12.8 MB
__device__ int   g_deg[NN];
__device__ float g_dis[NN];
__device__ int   g_idx64;           // 1 if edge_index is int64, 0 if int32

// ---------------- 0. index dtype detection ----------------
// If data is int64 (values in [0,N)), int64 reads are all valid.
// If data is int32, an int64 read packs two random edge ids -> >= 2^32 almost surely.
__global__ void detect_idx_kernel(const void* __restrict__ ei) {
    const long long* p = (const long long*)ei;
    int bad = 0;
    for (int i = threadIdx.x; i < 128; i += 32) {
        long long v = p[i];
        if (v < 0 || v >= NN) bad = 1;
    }
    bad = __any_sync(0xFFFFFFFF, bad);
    if (threadIdx.x == 0) g_idx64 = bad ? 0 : 1;
}

__device__ __forceinline__ int load_idx(const void* ei, long long pos) {
    if (g_idx64) return (int)((const long long*)ei)[pos];
    return ((const int*)ei)[pos];
}

// ---------------- 1. spectral norm sigma ----------------
// sigma = || W @ normalize(W^T u) ||
__global__ void sigma_kernel(const float* __restrict__ W, const float* __restrict__ u) {
    __shared__ float v[FIN];
    __shared__ float red[FIN];
    int t = threadIdx.x;  // 128 threads

    float s = 0.f;
#pragma unroll
    for (int j = 0; j < FOUT; j++) s += W[j * FIN + t] * u[j];
    v[t] = s;
    red[t] = s * s;
    __syncthreads();
    for (int off = 64; off > 0; off >>= 1) {
        if (t < off) red[t] += red[t + off];
        __syncthreads();
    }
    float inv_nv = rsqrtf(fmaxf(red[0], 1e-24f));
    __syncthreads();

    float wv = 0.f;
    if (t < FOUT) {
#pragma unroll
        for (int k = 0; k < FIN; k++) wv += W[t * FIN + k] * v[k];
        wv *= inv_nv;
    }
    red[t] = (t < FOUT) ? wv * wv : 0.f;
    __syncthreads();
    for (int off = 64; off > 0; off >>= 1) {
        if (t < off) red[t] += red[t + off];
        __syncthreads();
    }
    if (t == 0) {
        float sigma = sqrtf(red[0]);
        g_inv_sigma = 1.0f / fmaxf(sigma, 1e-12f);
    }
}

// ---------------- 2. degree ----------------
__global__ void zero_deg_kernel() {
    int i = blockIdx.x * 256 + threadIdx.x;
    if (i < NN) g_deg[i] = 0;
}

__global__ void degree_kernel(const void* __restrict__ ei) {
    int e = blockIdx.x * 256 + threadIdx.x;
    if (e < EE) {
        int c = load_idx(ei, (long long)EE + e);
        atomicAdd(&g_deg[c], 1);
    }
}

__global__ void dis_kernel() {
    int i = blockIdx.x * 256 + threadIdx.x;
    if (i < NN) g_dis[i] = rsqrtf((float)(g_deg[i] + 1));  // +1 = self loop
}

// ---------------- 3. GEMM  xw = (x @ W^T) * inv_sigma ----------------
// block: 256 threads, 32 nodes; thread -> (node = tid/8, 4 outputs = (tid%8)*4)
__global__ void gemm_kernel(const float* __restrict__ x, const float* __restrict__ W) {
    __shared__ float xs[32][132];       // padded
    __shared__ float wt[FIN][FOUT];     // W transposed: wt[k][j]
    int tid = threadIdx.x;
    int n0 = blockIdx.x * 32;

    for (int i = tid; i < FIN * FOUT; i += 256) {
        int j = i >> 7, k = i & 127;
        wt[k][j] = W[i];
    }
    const float4* x4 = (const float4*)x;
    for (int i = tid; i < 32 * 32; i += 256) {
        int n = i >> 5, kc = i & 31;
        int gn = n0 + n;
        float4 vv = make_float4(0.f, 0.f, 0.f, 0.f);
        if (gn < NN) vv = x4[gn * 32 + kc];
        *(float4*)&xs[n][kc * 4] = vv;
    }
    __syncthreads();

    float isig = g_inv_sigma;
    int n  = tid >> 3;
    int j0 = (tid & 7) << 2;
    float a0 = 0.f, a1 = 0.f, a2 = 0.f, a3 = 0.f;

#pragma unroll
    for (int kc = 0; kc < 32; kc++) {
        float4 xv = *(const float4*)&xs[n][kc << 2];
        float4 w0 = *(const float4*)&wt[(kc << 2) + 0][j0];
        float4 w1 = *(const float4*)&wt[(kc << 2) + 1][j0];
        float4 w2 = *(const float4*)&wt[(kc << 2) + 2][j0];
        float4 w3 = *(const float4*)&wt[(kc << 2) + 3][j0];
        a0 += xv.x * w0.x + xv.y * w1.x + xv.z * w2.x + xv.w * w3.x;
        a1 += xv.x * w0.y + xv.y * w1.y + xv.z * w2.y + xv.w * w3.y;
        a2 += xv.x * w0.z + xv.y * w1.z + xv.z * w2.z + xv.w * w3.z;
        a3 += xv.x * w0.w + xv.y * w1.w + xv.z * w2.w + xv.w * w3.w;
    }

    int gn = n0 + n;
    if (gn < NN) {
        float4 r;
        r.x = a0 * isig; r.y = a1 * isig; r.z = a2 * isig; r.w = a3 * isig;
        *(float4*)&g_xw[gn * FOUT + j0] = r;
    }
}

// ---------------- 4. self-loop init: out = xw / deg ----------------
__global__ void init_out_kernel(float* __restrict__ out) {
    int idx = blockIdx.x * 256 + threadIdx.x;  // NN*8 float4s
    if (idx >= NN * 8) return;
    int n = idx >> 3;
    float d = g_dis[n];
    float s = d * d;
    float4 v = ((const float4*)g_xw)[idx];
    v.x *= s; v.y *= s; v.z *= s; v.w *= s;
    ((float4*)out)[idx] = v;
}

// ---------------- 5. edge scatter: out[col] += xw[row]*dis[row]*dis[col] ----------------
// 8 threads per edge; each does one float4 gather + one v4 RED.
__global__ void scatter_kernel(const void* __restrict__ ei, float* __restrict__ out) {
    long long idx = (long long)blockIdx.x * 256 + threadIdx.x;
    long long e = idx >> 3;
    if (e >= EE) return;
    int q = (int)(idx & 7);
    int r = load_idx(ei, e);
    int c = load_idx(ei, (long long)EE + e);
    float nm = g_dis[r] * g_dis[c];
    float4 v = ((const float4*)g_xw)[r * 8 + q];
    float4* o = ((float4*)out) + c * 8 + q;
    asm volatile("red.global.add.v4.f32 [%0], {%1,%2,%3,%4};"
                 :: "l"(o), "f"(v.x * nm), "f"(v.y * nm), "f"(v.z * nm), "f"(v.w * nm)
                 : "memory");
}

// ---------------- 6. bias + PReLU ----------------
__global__ void finalize_kernel(float* __restrict__ out,
                                const float* __restrict__ bias,
                                const float* __restrict__ pa) {
    int idx = blockIdx.x * 256 + threadIdx.x;  // NN*8 float4s
    if (idx >= NN * 8) return;
    int q = idx & 7;
    float4 b = ((const float4*)bias)[q];
    float a = pa[0];
    float4 v = ((float4*)out)[idx];
    v.x += b.x; v.y += b.y; v.z += b.z; v.w += b.w;
    v.x = (v.x >= 0.f) ? v.x : a * v.x;
    v.y = (v.y >= 0.f) ? v.y : a * v.y;
    v.z = (v.z >= 0.f) ? v.z : a * v.z;
    v.w = (v.w >= 0.f) ? v.w : a * v.w;
    ((float4*)out)[idx] = v;
}

// ---------------- launch ----------------
extern "C" void kernel_launch(void* const* d_in, const int* in_sizes, int n_in,
                              void* d_out, int out_size) {
    const float* x    = (const float*)d_in[0];
    const void*  ei   = d_in[1];
    const float* W    = (const float*)d_in[2];
    const float* bias = (const float*)d_in[3];
    const float* pa   = (const float*)d_in[4];
    const float* u    = (const float*)d_in[5];
    float*       out  = (float*)d_out;

    detect_idx_kernel<<<1, 32>>>(ei);
    sigma_kernel<<<1, 128>>>(W, u);
    zero_deg_kernel<<<(NN + 255) / 256, 256>>>();
    degree_kernel<<<(EE + 255) / 256, 256>>>(ei);
    gemm_kernel<<<(NN + 31) / 32, 256>>>(x, W);
    dis_kernel<<<(NN + 255) / 256, 256>>>();
    init_out_kernel<<<(NN * 8 + 255) / 256, 256>>>(out);
    scatter_kernel<<<(int)((EE * 8LL + 255) / 256), 256>>>(ei, out);
    finalize_kernel<<<(NN * 8 + 255) / 256, 256>>>(out, bias, pa);
}